// round 12
// baseline (speedup 1.0000x reference)
#include <cuda_runtime.h>

#define NQ      14
#define STATE   16384
#define BATCH   512
#define THREADS 1024

typedef unsigned long long ull;

__device__ __forceinline__ int swz(int i) { return i ^ ((i >> 5) & 31); }

__device__ __forceinline__ float2 cmul(float2 a, float2 b) {
    return make_float2(a.x * b.x - a.y * b.y, a.x * b.y + a.y * b.x);
}

// ---- packed f32x2 (Blackwell FADD2 via PTX) ----
__device__ __forceinline__ ull pk(float x, float y) {
    ull r; asm("mov.b64 %0, {%1, %2};" : "=l"(r) : "f"(x), "f"(y)); return r;
}
__device__ __forceinline__ void upk(ull p, float& x, float& y) {
    asm("mov.b64 {%0, %1}, %2;" : "=f"(x), "=f"(y) : "l"(p));
}
__device__ __forceinline__ ull addx2(ull a, ull b) {
    ull r; asm("add.rn.f32x2 %0, %1, %2;" : "=l"(r) : "l"(a), "l"(b)); return r;
}
__device__ __forceinline__ ull subx2(ull a, ull b) {
    ull r; asm("sub.rn.f32x2 %0, %1, %2;" : "=l"(r) : "l"(a), "l"(b)); return r;
}

// Packed butterflies over register index bits: NE elems, NS stages.
template <int NE, int NS>
__device__ __forceinline__ void fwht_p(ull* v) {
#pragma unroll
    for (int s = 0; s < NS; s++) {
        const int h = 1 << s;
#pragma unroll
        for (int i = 0; i < NE / 2; i++) {
            const int k = i & (h - 1), g = (i >> s) << (s + 1);
            const int i0 = g + k, i1 = i0 + h;
            ull a = v[i0], b = v[i1];
            v[i0] = addx2(a, b);
            v[i1] = subx2(a, b);
        }
    }
}

// Real FWHT over 16 elements (4 bits), packed as pairs (k, k+8).
__device__ __forceinline__ void fwht_r16(float* r) {
    ull p[8];
#pragma unroll
    for (int k = 0; k < 8; k++) p[k] = pk(r[k], r[k + 8]);
    fwht_p<8, 3>(p);                       // h = 1,2,4 on both halves
#pragma unroll
    for (int k = 0; k < 8; k++) {          // h = 8: within-pack butterfly
        float x, y; upk(p[k], x, y);
        r[k]     = x + y;
        r[k + 8] = x - y;
    }
}

// SMEM layout (ull units): [0,STATE) data, fac(16), tabL(132 pad), tabH(128)
#define SM_FAC   (STATE)
#define SM_TABL  (STATE + 16)
#define SM_TABH  (STATE + 16 + 132)
#define SM_TOTAL (STATE + 16 + 132 + 128)

__global__ __launch_bounds__(THREADS, 1)
void rx_fused(const float* __restrict__ pr, const float* __restrict__ pim,
              const float* __restrict__ th, float* __restrict__ out,
              long long ocap) {
    extern __shared__ ull smu[];
    float*  smf  = (float*)smu;               // real-phase alias (first 64 KB)
    float2* fac  = (float2*)(smu + SM_FAC);
    float2* tabL = (float2*)(smu + SM_TABL);  // entry m at [m + (m>>5)]
    float2* tabH = (float2*)(smu + SM_TABH);

    const int b    = blockIdx.x;
    const int t    = threadIdx.x;
    const int lane = t & 31;
    const int w    = t >> 5;
    const int w0   = w & 1, w14 = w >> 1;

    if (t < NQ) {
        float s, c;
        __sincosf(-0.5f * th[b * NQ + t], &s, &c);
        fac[13 - t] = make_float2(c, s);      // bit p carries theta[13-p]
    }

    ull v[16];

    // ===== A: FWHT1 bits 10..13. idx = t + 1024j.
    {
        const float* prb = pr  + (size_t)b * STATE;
        const float* pib = pim + (size_t)b * STATE;
#pragma unroll
        for (int j = 0; j < 16; j++)
            v[j] = pk(prb[t + 1024 * j], pib[t + 1024 * j]);
    }
    __syncthreads();                           // fac visible

    if (t < 256) {                             // Kronecker half-tables
        const int m    = t & 127;
        const int base = (t < 128) ? 0 : 7;
        float2 e = (t < 128) ? make_float2(0x1p-14f, 0.f) : make_float2(1.f, 0.f);
#pragma unroll
        for (int k = 0; k < 7; k++)
            if ((m >> k) & 1) e = cmul(e, fac[base + k]);
        if (t < 128) tabL[m + (m >> 5)] = e;
        else         tabH[m]            = e;
    }

    fwht_p<16, 4>(v);
#pragma unroll
    for (int j = 0; j < 16; j++) smu[swz(t + 1024 * j)] = v[j];
    __syncthreads();

    // ===== B: FWHT1 bits 6..9. idx = lane + 32w0 + 64j + 1024w14.
    {
        const int base = lane + 32 * w0 + 1024 * w14;
#pragma unroll
        for (int j = 0; j < 16; j++) v[j] = smu[swz(base + 64 * j)];
        fwht_p<16, 4>(v);
#pragma unroll
        for (int j = 0; j < 16; j++) smu[swz(base + 64 * j)] = v[j];
    }
    __syncthreads();

    // ===== C: FWHT1 bits 2..5. idx = (lane&3) + 4j + 64w0 + 128(lane>>2) + 1024w14.
    {
        const int base = (lane & 3) + 64 * w0 + 128 * (lane >> 2) + 1024 * w14;
#pragma unroll
        for (int j = 0; j < 16; j++) v[j] = smu[swz(base + 4 * j)];
        fwht_p<16, 4>(v);
#pragma unroll
        for (int j = 0; j < 16; j++) smu[swz(base + 4 * j)] = v[j];
    }
    __syncthreads();

    // ===== D: FWHT1 bits 0..1, diag -> REAL, FWHT2 bits 0..3.
    //         idx = j + 16*(lane>>4) + 32*(lane&15) + 512*w.
    float r[16];
    {
        const int l4   = lane >> 4;
        const int base = 16 * l4 + 32 * (lane & 15) + 512 * w;
#pragma unroll
        for (int j = 0; j < 16; j++) v[j] = smu[swz(base + j)];
        fwht_p<4, 2>(v);  fwht_p<4, 2>(v + 4);       // FWHT1 bits 0..1
        fwht_p<4, 2>(v + 8); fwht_p<4, 2>(v + 12);

        const float2 hv = tabH[4 * w + ((lane >> 2) & 3)];
        const int    m0 = 16 * l4 + 32 * (lane & 3); // m = m0 + j, j<16 (no pad step)
#pragma unroll
        for (int j = 0; j < 16; j++) {
            const float2 e = cmul(hv, tabL[m0 + (m0 >> 5) + j]);
            float x, y; upk(v[j], x, y);
            r[j] = fmaf(x, e.x, -(y * e.y));         // Re(ev * w)
        }
        fwht_r16(r);                                  // FWHT2 bits 0..3
        __syncthreads();                              // complex reads done
#pragma unroll
        for (int j = 0; j < 16; j++) smf[swz(base + j)] = r[j];
    }
    __syncthreads();

    // ===== E: FWHT2 bits 4..7. idx = (lane&7) + 8w0 + 16j + 256(lane>>3) + 1024w14.
    {
        const int base = (lane & 7) + 8 * w0 + 256 * (lane >> 3) + 1024 * w14;
#pragma unroll
        for (int j = 0; j < 16; j++) r[j] = smf[swz(base + 16 * j)];
        fwht_r16(r);
#pragma unroll
        for (int j = 0; j < 16; j++) smf[swz(base + 16 * j)] = r[j];
    }
    __syncthreads();

    // ===== F: FWHT2 bits 8..11. idx = lane + 32(w&7) + 256j + 4096(w>>3).
    {
        const int base = lane + 32 * (w & 7) + 4096 * (w >> 3);
#pragma unroll
        for (int j = 0; j < 16; j++) r[j] = smf[swz(base + 256 * j)];
        fwht_r16(r);
#pragma unroll
        for (int j = 0; j < 16; j++) smf[swz(base + 256 * j)] = r[j];
    }
    __syncthreads();

    // ===== G: FWHT2 bits 12..13 (4 groups of 4); write real plane.
    {
        float* ob = out + (size_t)b * STATE;
        const long long rb = (long long)b * STATE;
#pragma unroll
        for (int i = 0; i < 4; i++) {
            float q[4];
#pragma unroll
            for (int jp = 0; jp < 4; jp++)
                q[jp] = smf[swz(t + 1024 * i + 4096 * jp)];
            // 2-stage FWHT over jp
            float a0 = q[0] + q[1], a1 = q[0] - q[1];
            float a2 = q[2] + q[3], a3 = q[2] - q[3];
            q[0] = a0 + a2; q[2] = a0 - a2;
            q[1] = a1 + a3; q[3] = a1 - a3;
#pragma unroll
            for (int jp = 0; jp < 4; jp++) {
                const long long idx = rb + t + 1024 * i + 4096 * jp;
                if (idx < ocap) ob[t + 1024 * i + 4096 * jp] = q[jp];
            }
        }
    }
}

extern "C" void kernel_launch(void* const* d_in, const int* in_sizes, int n_in,
                              void* d_out, int out_size) {
    // Contract (established R8): fp32 planar inputs; output = fp32 REAL part.
    int ia = -1, ib = -1, ith = -1;
    for (int k = 0; k < n_in && ith < 0; k++) {
        const long long st = in_sizes[k];
        if (st <= 0 || (st * 8192) % 7) continue;
        const long long sp = st * 8192 / 7;
        int a = -1, bb = -1;
        for (int j = 0; j < n_in; j++) {
            if (j == k) continue;
            if ((long long)in_sizes[j] == sp) { if (a < 0) a = j; else if (bb < 0) bb = j; }
        }
        if (a >= 0 && bb >= 0) { ith = k; ia = a; ib = bb; }
    }
    if (ith < 0) { if (n_in < 3) return; ia = 0; ib = 1; ith = 2; }

    const size_t smem = SM_TOTAL * sizeof(ull);   // 133,280 B
    if (cudaFuncSetAttribute(rx_fused,
            cudaFuncAttributeMaxDynamicSharedMemorySize, (int)smem) != cudaSuccess)
        return;
    rx_fused<<<BATCH, THREADS, smem>>>(
        (const float*)d_in[ia], (const float*)d_in[ib], (const float*)d_in[ith],
        (float*)d_out, (long long)out_size);
}